// round 11
// baseline (speedup 1.0000x reference)
#include <cuda_runtime.h>

// SinkhornMixer: M = sigmoid(L)+I; 5x {row norm; col norm}.
// M = diag(r)*(S+I)*diag(c); S quantized u8 (s ~= (q+0.5)/256), stored BOTH
// row-major (S8) and transposed (S8T). All 9 interior matvecs are u8xu8
// __dp4a row-dots (exact int32 accumulation) against fixed-scale-quantized
// r/c vectors held in SMEM; S loads are explicitly batched 8-deep for MLP.
// Per-iteration scalar slots g_rsum[]/g_csum[] carry +0.5-bias corrections.
// Final output recomputes sigmoid(L) in fp32.

#define N 8192
#define EPS 1e-6f
#define RMAX 5e-4f            // fixed quant ranges; true r ~ 2.44e-4, c ~ 1.0
#define CMAX 2.0f
#define RQ (255.0f / RMAX)
#define CQ (255.0f / CMAX)
#define RSCALE (RMAX / (255.0f * 256.0f))  // idot -> (sum q*r)/256
#define CSCALE (CMAX / (255.0f * 256.0f))

__device__ unsigned char g_S8 [(size_t)N * N];  // 64 MB row-major
__device__ unsigned char g_S8T[(size_t)N * N];  // 64 MB transposed
__device__ float g_r[N];
__device__ float g_c[N];
__device__ unsigned char g_ru8[N];
__device__ unsigned char g_cu8[N];
__device__ float g_rsum[6];   // rsum[0]=pass0; rowS(it) writes rsum[it+1]
__device__ float g_csum[6];   // colT(it) writes csum[it]

__device__ __forceinline__ float sigmoidf(float x) {
    return 1.0f / (1.0f + __expf(-x));
}

__device__ __forceinline__ float warp_reduce_f(float v) {
    #pragma unroll
    for (int off = 16; off > 0; off >>= 1)
        v += __shfl_down_sync(0xffffffffu, v, off);
    return v;
}
__device__ __forceinline__ unsigned warp_reduce_u(unsigned v) {
    #pragma unroll
    for (int off = 16; off > 0; off >>= 1)
        v += __shfl_down_sync(0xffffffffu, v, off);
    return v;
}

__device__ __forceinline__ unsigned char quant_byte(float v, float scale) {
    int u = __float2int_rn(v * scale);
    u = max(0, min(255, u));
    return (unsigned char)u;
}

// ---- init: zero per-iteration scalar slots (graph-replay safe) --------------
__global__ void k_init() {
    if (threadIdx.x < 6) { g_rsum[threadIdx.x] = 0.0f; g_csum[threadIdx.x] = 0.0f; }
}

// ---- pass 0: S8 = quant(sigmoid(L)); exact fp32 rowsum -> r1; c = 1 ---------
__global__ void __launch_bounds__(256) k_pass0(const float* __restrict__ L) {
    __shared__ float sm[8];
    int row = blockIdx.x;
    const float4* Lr = (const float4*)(L + (size_t)row * N);
    unsigned int* Sr = (unsigned int*)(g_S8 + (size_t)row * N);
    int t = threadIdx.x, lane = t & 31, w = t >> 5;
    float acc = 0.0f;
    #pragma unroll
    for (int k = 0; k < 8; k++) {
        float4 v = __ldcs(&Lr[t + k * 256]);
        float s0 = sigmoidf(v.x), s1 = sigmoidf(v.y);
        float s2 = sigmoidf(v.z), s3 = sigmoidf(v.w);
        acc += (s0 + s1) + (s2 + s3);
        unsigned q0 = min(255u, (unsigned)(s0 * 256.0f));
        unsigned q1 = min(255u, (unsigned)(s1 * 256.0f));
        unsigned q2 = min(255u, (unsigned)(s2 * 256.0f));
        unsigned q3 = min(255u, (unsigned)(s3 * 256.0f));
        Sr[t + k * 256] = q0 | (q1 << 8) | (q2 << 16) | (q3 << 24);
    }
    float v = warp_reduce_f(acc);
    if (lane == 0) sm[w] = v;
    __syncthreads();
    if (w == 0) {
        v = (lane < 8) ? sm[lane] : 0.0f;
        v = warp_reduce_f(v);
        if (lane == 0) {
            float rv = 1.0f / (v + 1.0f + EPS);   // identity, c=1, r was 1
            g_r[row]   = rv;
            g_ru8[row] = quant_byte(rv, RQ);
            g_c[row]   = 1.0f;
            atomicAdd(&g_rsum[0], rv);
        }
    }
}

// ---- transpose S8 -> S8T (64x64 u8 tiles via padded smem) -------------------
__global__ void __launch_bounds__(256) k_transpose() {
    __shared__ unsigned char sm[64][80];  // row stride 80 (16B-aligned, padded)
    int t  = threadIdx.x;
    int c0 = blockIdx.x * 64;     // source col tile
    int r0 = blockIdx.y * 64;     // source row tile
    int lr  = t >> 2;             // 0..63
    int lc4 = (t & 3) * 16;       // 0,16,32,48
    uint4 v = *(const uint4*)(g_S8 + (size_t)(r0 + lr) * N + c0 + lc4);
    const unsigned char* pv = (const unsigned char*)&v;
    #pragma unroll
    for (int k = 0; k < 16; k++) sm[lc4 + k][lr] = pv[k];  // sm[x][y]=S8[r0+y][c0+x]
    __syncthreads();
    uint4 wv = *(const uint4*)&sm[lr][lc4];  // bytes S8[r0+lc4+k][c0+lr]
    *(uint4*)(g_S8T + (size_t)(c0 + lr) * N + r0 + lc4) = wv;
}

// ---- generic dp4a row sweep: acc = dot(Mrow, vec_smem), batched loads -------
__device__ __forceinline__ unsigned dp4a_row(const uint4* __restrict__ Mr,
                                             const uint4* __restrict__ vec,
                                             int lane) {
    unsigned a0 = 0, a1 = 0, a2 = 0, a3 = 0;
    #pragma unroll
    for (int half = 0; half < 2; half++) {
        uint4 s[8];
        #pragma unroll
        for (int k = 0; k < 8; k++)
            s[k] = __ldg(&Mr[lane + (half * 8 + k) * 32]);
        #pragma unroll
        for (int k = 0; k < 8; k++) {
            uint4 u = vec[lane + (half * 8 + k) * 32];
            a0 = __dp4a(s[k].x, u.x, a0);
            a1 = __dp4a(s[k].y, u.y, a1);
            a2 = __dp4a(s[k].z, u.z, a2);
            a3 = __dp4a(s[k].w, u.w, a3);
        }
    }
    return (a0 + a1) + (a2 + a3);
}

// ---- col step: warp-per-row of S8T: z_j = sum_i q_ij r_i, c update ----------
__global__ void __launch_bounds__(256) k_colT(int it) {
    __shared__ uint4 vec[512];            // 8KB: g_ru8 staged
    int t = threadIdx.x, lane = t & 31, w = t >> 5;
    {
        const uint4* RU = (const uint4*)g_ru8;
        vec[t]       = __ldg(&RU[t]);
        vec[t + 256] = __ldg(&RU[t + 256]);
    }
    __syncthreads();
    int j = blockIdx.x * 8 + w;           // column of S == row of S8T
    const uint4* Tr = (const uint4*)(g_S8T + (size_t)j * N);
    unsigned id = warp_reduce_u(dp4a_row(Tr, vec, lane));
    if (lane == 0) {
        float dot = (float)id * RSCALE + g_rsum[it] * (1.0f / 512.0f);
        float u   = dot + g_r[j];         // identity contribution
        float cv  = g_c[j];
        float cn  = cv / (cv * u + EPS);
        g_c[j]    = cn;
        g_cu8[j]  = quant_byte(cn, CQ);
        atomicAdd(&g_csum[it], cn);
    }
}

// ---- row step: warp-per-row of S8: y_i = sum_j q_ij c_j, r update -----------
__global__ void __launch_bounds__(256) k_rowS(int it) {
    __shared__ uint4 vec[512];            // 8KB: g_cu8 staged
    int t = threadIdx.x, lane = t & 31, w = t >> 5;
    {
        const uint4* CU = (const uint4*)g_cu8;
        vec[t]       = __ldg(&CU[t]);
        vec[t + 256] = __ldg(&CU[t + 256]);
    }
    __syncthreads();
    int row = blockIdx.x * 8 + w;
    const uint4* Sr = (const uint4*)(g_S8 + (size_t)row * N);
    unsigned id = warp_reduce_u(dp4a_row(Sr, vec, lane));
    if (lane == 0) {
        float dot = (float)id * CSCALE + g_csum[it] * (1.0f / 512.0f);
        float y   = dot + g_c[row];       // identity contribution
        float rv  = g_r[row];
        float rn  = rv / (rv * y + EPS);
        g_r[row]   = rn;
        g_ru8[row] = quant_byte(rn, RQ);
        atomicAdd(&g_rsum[it + 1], rn);
    }
}

// ---- final: out_ij = r_i * (sigmoid(L_ij) + (i==j)) * c_j  (full fp32) ------
__global__ void __launch_bounds__(256) k_final(const float* __restrict__ L,
                                               float* __restrict__ out) {
    int row = blockIdx.x;
    float ri = g_r[row];
    const float4* Lr = (const float4*)(L + (size_t)row * N);
    const float4* C4 = (const float4*)g_c;
    float4*       Or = (float4*)(out + (size_t)row * N);
    int t = threadIdx.x;
    int diag4 = row >> 2;
    int diagc = row & 3;
    #pragma unroll
    for (int k = 0; k < 8; k++) {
        int idx = t + k * 256;
        float4 v = __ldcs(&Lr[idx]);
        float4 c = C4[idx];
        float4 o;
        o.x = ri * sigmoidf(v.x) * c.x;
        o.y = ri * sigmoidf(v.y) * c.y;
        o.z = ri * sigmoidf(v.z) * c.z;
        o.w = ri * sigmoidf(v.w) * c.w;
        if (idx == diag4) {
            float add = ri * ((const float*)C4)[row];
            if (diagc == 0) o.x += add;
            else if (diagc == 1) o.y += add;
            else if (diagc == 2) o.z += add;
            else o.w += add;
        }
        __stcs(&Or[idx], o);
    }
}

extern "C" void kernel_launch(void* const* d_in, const int* in_sizes, int n_in,
                              void* d_out, int out_size) {
    const float* L = (const float*)d_in[0];
    float* out = (float*)d_out;

    k_init<<<1, 32>>>();
    k_pass0<<<N, 256>>>(L);                    // S8 + r1 (row step 1), c=1
    k_transpose<<<dim3(128, 128), 256>>>();    // S8 -> S8T

    k_colT<<<N / 8, 256>>>(0);                 // col step 1
    for (int it = 0; it < 4; it++) {
        k_rowS<<<N / 8, 256>>>(it);            // row step it+2
        k_colT<<<N / 8, 256>>>(it + 1);        // col step it+2
    }

    k_final<<<N, 256>>>(L, out);
}

// round 12
// speedup vs baseline: 1.1268x; 1.1268x over previous
#include <cuda_runtime.h>

// SinkhornMixer: M = sigmoid(L)+I; 5x {row norm; col norm}.
// M = diag(r)*(S+I)*diag(c); S quantized u8 (s ~= (q+0.5)/256), stored
// row-major (S8) and transposed (S8T). Interior matvecs are u8xu8 __dp4a
// BLOCK-per-row sweeps (2M threads -> max outstanding loads). Col step 1 is
// fused into the transpose (tile already in smem). Per-iteration scalar
// slots g_rsum[]/g_csum[] carry the +0.5-bias corrections (graph-safe).
// Final output recomputes sigmoid(L) in fp32.

#define N 8192
#define EPS 1e-6f
#define RMAX 5e-4f            // fixed quant ranges; true r ~ 2.44e-4, c ~ 1.0
#define CMAX 2.0f
#define RQ (255.0f / RMAX)
#define CQ (255.0f / CMAX)
#define RSCALE (RMAX / (255.0f * 256.0f))  // idot -> (sum q*r)/256
#define CSCALE (CMAX / (255.0f * 256.0f))

__device__ unsigned char g_S8 [(size_t)N * N];  // 64 MB row-major
__device__ unsigned char g_S8T[(size_t)N * N];  // 64 MB transposed
__device__ float g_r[N];
__device__ float g_c[N];
__device__ unsigned char g_ru8[N];
__device__ unsigned char g_cu8[N];
__device__ float g_z[N];      // col-step-1 partials (fp32, from transpose)
__device__ float g_rsum[6];   // rsum[0]=pass0; rowS(it) writes rsum[it+1]
__device__ float g_csum[6];   // csum[0]=updc1; colT(it) writes csum[it+1]

__device__ __forceinline__ float sigmoidf(float x) {
    return 1.0f / (1.0f + __expf(-x));
}

__device__ __forceinline__ float warp_reduce_f(float v) {
    #pragma unroll
    for (int off = 16; off > 0; off >>= 1)
        v += __shfl_down_sync(0xffffffffu, v, off);
    return v;
}
__device__ __forceinline__ unsigned warp_reduce_u(unsigned v) {
    #pragma unroll
    for (int off = 16; off > 0; off >>= 1)
        v += __shfl_down_sync(0xffffffffu, v, off);
    return v;
}

__device__ __forceinline__ unsigned char quant_byte(float v, float scale) {
    int u = __float2int_rn(v * scale);
    u = max(0, min(255, u));
    return (unsigned char)u;
}

// ---- init: zero z + scalar slots (graph-replay safe) ------------------------
__global__ void __launch_bounds__(1024) k_init() {
    int j = blockIdx.x * 1024 + threadIdx.x;
    if (j < N) g_z[j] = 0.0f;
    if (j < 6) { g_rsum[j] = 0.0f; g_csum[j] = 0.0f; }
}

// ---- pass 0: S8 = quant(sigmoid(L)); exact fp32 rowsum -> r1; c = 1 ---------
__global__ void __launch_bounds__(256) k_pass0(const float* __restrict__ L) {
    __shared__ float sm[8];
    int row = blockIdx.x;
    const float4* Lr = (const float4*)(L + (size_t)row * N);
    unsigned int* Sr = (unsigned int*)(g_S8 + (size_t)row * N);
    int t = threadIdx.x, lane = t & 31, w = t >> 5;
    float acc = 0.0f;
    #pragma unroll
    for (int k = 0; k < 8; k++) {
        float4 v = __ldcs(&Lr[t + k * 256]);
        float s0 = sigmoidf(v.x), s1 = sigmoidf(v.y);
        float s2 = sigmoidf(v.z), s3 = sigmoidf(v.w);
        acc += (s0 + s1) + (s2 + s3);
        unsigned q0 = min(255u, (unsigned)(s0 * 256.0f));
        unsigned q1 = min(255u, (unsigned)(s1 * 256.0f));
        unsigned q2 = min(255u, (unsigned)(s2 * 256.0f));
        unsigned q3 = min(255u, (unsigned)(s3 * 256.0f));
        Sr[t + k * 256] = q0 | (q1 << 8) | (q2 << 16) | (q3 << 24);
    }
    float v = warp_reduce_f(acc);
    if (lane == 0) sm[w] = v;
    __syncthreads();
    if (w == 0) {
        v = (lane < 8) ? sm[lane] : 0.0f;
        v = warp_reduce_f(v);
        if (lane == 0) {
            float rv = 1.0f / (v + 1.0f + EPS);   // identity, c=1, r was 1
            g_r[row]   = rv;
            g_ru8[row] = quant_byte(rv, RQ);
            g_c[row]   = 1.0f;
            atomicAdd(&g_rsum[0], rv);
        }
    }
}

// ---- transpose S8 -> S8T + fused col-step-1 partials (fp32 r) ---------------
__global__ void __launch_bounds__(256) k_transpose() {
    __shared__ unsigned char sm[64][80];  // sm[x][y] = S8[r0+y][c0+x]
    __shared__ float rf[64];
    __shared__ float zp[64];
    int t  = threadIdx.x;
    int c0 = blockIdx.x * 64;     // source col tile
    int r0 = blockIdx.y * 64;     // source row tile
    if (t < 64) { rf[t] = g_r[r0 + t]; zp[t] = 0.0f; }
    int lr  = t >> 2;             // 0..63
    int lc4 = (t & 3) * 16;       // 0,16,32,48
    uint4 v = *(const uint4*)(g_S8 + (size_t)(r0 + lr) * N + c0 + lc4);
    const unsigned char* pv = (const unsigned char*)&v;
    #pragma unroll
    for (int k = 0; k < 16; k++) sm[lc4 + k][lr] = pv[k];
    __syncthreads();
    // transposed write
    uint4 wv = *(const uint4*)&sm[lr][lc4];
    *(uint4*)(g_S8T + (size_t)(c0 + lr) * N + r0 + lc4) = wv;
    // fused col partial: z_{c0+x} += sum_y q * r  (raw q dot, fp32 r)
    int x  = t & 63;
    int ya = (t >> 6) * 16;       // 4 threads per column, 16 rows each
    uint4 sv = *(const uint4*)&sm[x][ya];   // row stride 80 is 16B-multiple
    const unsigned char* pb = (const unsigned char*)&sv;
    float p = 0.0f;
    #pragma unroll
    for (int k = 0; k < 16; k++) p += (float)pb[k] * rf[ya + k];
    atomicAdd(&zp[x], p);
    __syncthreads();
    if (t < 64) atomicAdd(&g_z[c0 + t], zp[t]);
}

// ---- c update for col step 1: u = z/256 + rsum0/512 + r_j -------------------
__global__ void __launch_bounds__(1024) k_updc1() {
    __shared__ float sm[32];
    int t = threadIdx.x, lane = t & 31, w = t >> 5;
    int j = blockIdx.x * 1024 + t;
    float R = g_rsum[0];
    float u  = g_z[j] * (1.0f / 256.0f) + R * (1.0f / 512.0f) + g_r[j];
    float cv = g_c[j];
    float cn = cv / (cv * u + EPS);
    g_c[j]   = cn;
    g_cu8[j] = quant_byte(cn, CQ);
    float v = warp_reduce_f(cn);
    if (lane == 0) sm[w] = v;
    __syncthreads();
    if (w == 0) {
        v = (lane < 32) ? sm[lane] : 0.0f;
        v = warp_reduce_f(v);
        if (lane == 0) atomicAdd(&g_csum[0], v);
    }
}

// ---- block-per-row dp4a dot helper (row of 8192 u8 = 512 uint4) -------------
__device__ __forceinline__ unsigned dp4a_block_dot(
        const uint4* __restrict__ Mr, const uint4* __restrict__ vec) {
    __shared__ unsigned sm[8];
    int t = threadIdx.x, lane = t & 31, w = t >> 5;
    uint4 s0 = __ldg(&Mr[t]);
    uint4 s1 = __ldg(&Mr[t + 256]);
    uint4 u0 = __ldg(&vec[t]);
    uint4 u1 = __ldg(&vec[t + 256]);
    unsigned a = 0, b = 0;
    a = __dp4a(s0.x, u0.x, a);
    b = __dp4a(s0.y, u0.y, b);
    a = __dp4a(s0.z, u0.z, a);
    b = __dp4a(s0.w, u0.w, b);
    a = __dp4a(s1.x, u1.x, a);
    b = __dp4a(s1.y, u1.y, b);
    a = __dp4a(s1.z, u1.z, a);
    b = __dp4a(s1.w, u1.w, b);
    unsigned v = warp_reduce_u(a + b);
    if (lane == 0) sm[w] = v;
    __syncthreads();
    if (w == 0) {
        v = (lane < 8) ? sm[lane] : 0u;
        v = warp_reduce_u(v);
    }
    return v;  // valid in thread 0
}

// ---- row step (block-per-row of S8): y_i = sum_j q_ij c_j, r update ---------
__global__ void __launch_bounds__(256) k_rowS(int it) {
    int row = blockIdx.x;
    unsigned id = dp4a_block_dot((const uint4*)(g_S8 + (size_t)row * N),
                                 (const uint4*)g_cu8);
    if (threadIdx.x == 0) {
        float dot = (float)id * CSCALE + g_csum[it] * (1.0f / 512.0f);
        float y   = dot + g_c[row];           // identity contribution
        float rv  = g_r[row];
        float rn  = rv / (rv * y + EPS);
        g_r[row]   = rn;
        g_ru8[row] = quant_byte(rn, RQ);
        atomicAdd(&g_rsum[it + 1], rn);
    }
}

// ---- col step (block-per-row of S8T): z_j = sum_i q_ij r_i, c update --------
__global__ void __launch_bounds__(256) k_colT(int it) {
    int j = blockIdx.x;
    unsigned id = dp4a_block_dot((const uint4*)(g_S8T + (size_t)j * N),
                                 (const uint4*)g_ru8);
    if (threadIdx.x == 0) {
        float dot = (float)id * RSCALE + g_rsum[it + 1] * (1.0f / 512.0f);
        float u   = dot + g_r[j];             // identity contribution
        float cv  = g_c[j];
        float cn  = cv / (cv * u + EPS);
        g_c[j]    = cn;
        g_cu8[j]  = quant_byte(cn, CQ);
        atomicAdd(&g_csum[it + 1], cn);
    }
}

// ---- final: out_ij = r_i * (sigmoid(L_ij) + (i==j)) * c_j  (full fp32) ------
__global__ void __launch_bounds__(256) k_final(const float* __restrict__ L,
                                               float* __restrict__ out) {
    int row = blockIdx.x;
    float ri = g_r[row];
    const float4* Lr = (const float4*)(L + (size_t)row * N);
    const float4* C4 = (const float4*)g_c;
    float4*       Or = (float4*)(out + (size_t)row * N);
    int t = threadIdx.x;
    int diag4 = row >> 2;
    int diagc = row & 3;
    #pragma unroll
    for (int k = 0; k < 8; k++) {
        int idx = t + k * 256;
        float4 v = __ldcs(&Lr[idx]);
        float4 c = C4[idx];
        float4 o;
        o.x = ri * sigmoidf(v.x) * c.x;
        o.y = ri * sigmoidf(v.y) * c.y;
        o.z = ri * sigmoidf(v.z) * c.z;
        o.w = ri * sigmoidf(v.w) * c.w;
        if (idx == diag4) {
            float add = ri * ((const float*)C4)[row];
            if (diagc == 0) o.x += add;
            else if (diagc == 1) o.y += add;
            else if (diagc == 2) o.z += add;
            else o.w += add;
        }
        __stcs(&Or[idx], o);
    }
}

extern "C" void kernel_launch(void* const* d_in, const int* in_sizes, int n_in,
                              void* d_out, int out_size) {
    const float* L = (const float*)d_in[0];
    float* out = (float*)d_out;

    k_init<<<8, 1024>>>();
    k_pass0<<<N, 256>>>(L);                    // S8 + row step 1 (c = 1)
    k_transpose<<<dim3(128, 128), 256>>>();    // S8 -> S8T  + col-1 partials
    k_updc1<<<8, 1024>>>();                    // col step 1 finalize

    for (int it = 0; it < 4; it++) {
        k_rowS<<<N, 256>>>(it);                // row step it+2
        k_colT<<<N, 256>>>(it);                // col step it+2
    }

    k_final<<<N, 256>>>(L, out);
}